// round 3
// baseline (speedup 1.0000x reference)
#include <cuda_runtime.h>
#include <math.h>

// Shapes (fixed per reference)
#define BB 2
#define NN 64
#define MM 64
#define LL 30
#define EE 128
#define HH 4
#define DHH 32
#define KD 136        // 120 softmax-weight rows + 16 ew rows
#define SST 68        // S row stride (64 m, padded)

// ---------------- device scratch (no allocation allowed) ----------------
__device__ __align__(16) float g_W2[EE * EE];     // Wo @ Wp
__device__ __align__(16) float g_WeK[4 * EE];     // We @ Wk
__device__ __align__(16) float g_WeV[4 * EE];     // We @ Wv
__device__ __align__(16) float g_ck[LL * EE];     // (be+pe[l])@Wk + bk
__device__ __align__(16) float g_cv[LL * EE];     // (be+pe[l])@Wv + bv
__device__ __align__(16) float g_b2[EE];          // bo@Wp + bp
__device__ __align__(16) float g_ae[BB * NN * EE];
__device__ __align__(16) float g_q[BB * NN * EE];
__device__ __align__(16) float g_C[KD * EE];      // folded epilogue matrix

// ---------------- f32x2 packed helpers (Blackwell FFMA2) ----------------
__device__ __forceinline__ unsigned long long pk2(float a, float b) {
    unsigned long long r;
    asm("mov.b64 %0, {%1,%2};" : "=l"(r) : "f"(a), "f"(b));
    return r;
}
__device__ __forceinline__ void fma2(unsigned long long& d, unsigned long long a,
                                     unsigned long long b) {
    asm("fma.rn.f32x2 %0, %1, %2, %0;" : "+l"(d) : "l"(a), "l"(b));
}
__device__ __forceinline__ void upk2(unsigned long long v, float& a, float& b) {
    asm("mov.b64 {%0,%1}, %2;" : "=f"(a), "=f"(b) : "l"(v));
}

// ======================= P1: independent precomputes =====================
// outputs: g_W2, g_WeK, g_WeV, g_ck, g_cv, g_b2, g_ae
__global__ void p1_kernel(const float* __restrict__ agent,
                          const float* __restrict__ We, const float* __restrict__ be,
                          const float* __restrict__ Wa, const float* __restrict__ ba,
                          const float* __restrict__ pe,
                          const float* __restrict__ Wk, const float* __restrict__ bk,
                          const float* __restrict__ Wv, const float* __restrict__ bv,
                          const float* __restrict__ Wo, const float* __restrict__ bo,
                          const float* __restrict__ Wp, const float* __restrict__ bp) {
    int id = blockIdx.x * blockDim.x + threadIdx.x;

    if (id < EE * EE) {  // W2[i][j] = sum_t Wo[i][t] Wp[t][j]
        int i = id >> 7, j = id & 127;
        float a = 0.f;
#pragma unroll 8
        for (int t = 0; t < EE; t++) a += Wo[i * EE + t] * Wp[t * EE + j];
        g_W2[id] = a;
        return;
    }
    id -= EE * EE;
    if (id < 4 * EE) {  // WeK
        int c = id >> 7, j = id & 127;
        float a = 0.f;
#pragma unroll 8
        for (int i = 0; i < EE; i++) a += We[c * EE + i] * Wk[i * EE + j];
        g_WeK[id] = a;
        return;
    }
    id -= 4 * EE;
    if (id < 4 * EE) {  // WeV
        int c = id >> 7, j = id & 127;
        float a = 0.f;
#pragma unroll 8
        for (int i = 0; i < EE; i++) a += We[c * EE + i] * Wv[i * EE + j];
        g_WeV[id] = a;
        return;
    }
    id -= 4 * EE;
    if (id < LL * EE) {  // ck
        int l = id >> 7, j = id & 127;
        float a = bk[j];
#pragma unroll 8
        for (int i = 0; i < EE; i++) a += (be[i] + pe[l * EE + i]) * Wk[i * EE + j];
        g_ck[id] = a;
        return;
    }
    id -= LL * EE;
    if (id < LL * EE) {  // cv
        int l = id >> 7, j = id & 127;
        float a = bv[j];
#pragma unroll 8
        for (int i = 0; i < EE; i++) a += (be[i] + pe[l * EE + i]) * Wv[i * EE + j];
        g_cv[id] = a;
        return;
    }
    id -= LL * EE;
    if (id < EE) {  // b2 = bo@Wp + bp
        float a = bp[id];
#pragma unroll 8
        for (int t = 0; t < EE; t++) a += bo[t] * Wp[t * EE + id];
        g_b2[id] = a;
        return;
    }
    id -= EE;
    if (id < BB * NN * EE) {  // ae = afeat@Wa + ba ; afeat = agent[{2,5..15}]
        int bnq = id >> 7, j = id & 127;
        const float* ag = agent + bnq * 16;
        float a = ba[j] + ag[2] * Wa[0 * EE + j];
#pragma unroll
        for (int i = 1; i < 12; i++) a += ag[4 + i] * Wa[i * EE + j];
        g_ae[id] = a;
    }
}

// ======================= P2: dependent precomputes =======================
// q = ae@Wq + bq ; C = fold(cv, WeV) with W2
__global__ void p2_kernel(const float* __restrict__ Wq, const float* __restrict__ bq) {
    int id = blockIdx.x * blockDim.x + threadIdx.x;
    if (id < BB * NN * EE) {
        int bnq = id >> 7, j = id & 127;
        float a = bq[j];
        const float* ap = g_ae + bnq * EE;
#pragma unroll 8
        for (int i = 0; i < EE; i++) a += ap[i] * Wq[i * EE + j];
        g_q[id] = a;
        return;
    }
    id -= BB * NN * EE;
    if (id < KD * EE) {
        int k = id >> 7, e = id & 127;
        float a = 0.f;
        if (k < HH * LL) {
            int h = k / LL, l = k % LL;
            const float* cvp = g_cv + l * EE + h * DHH;
            const float* w2p = g_W2 + (h * DHH) * EE + e;
#pragma unroll
            for (int d = 0; d < DHH; d++) a += cvp[d] * w2p[d * EE];
        } else {
            int kk = k - HH * LL;
            int h = kk >> 2, c = kk & 3;
            const float* wev = g_WeV + c * EE + h * DHH;
            const float* w2p = g_W2 + (h * DHH) * EE + e;
#pragma unroll
            for (int d = 0; d < DHH; d++) a += wev[d] * w2p[d * EE];
        }
        g_C[id] = a;
    }
}

// ======================= main kernel: one block per (b,n) ================
// smem floats: C 17408 | S 136*68=9248 | q 128 | r 16 | s0 120 | ax/f1 8
#define SM_C 0
#define SM_S 17408
#define SM_Q (SM_S + KD * SST)
#define SM_R (SM_Q + EE)
#define SM_S0 (SM_R + 16)
#define SM_AX (SM_S0 + HH * LL)
#define SM_TOTAL_FLOATS (SM_AX + 8)

__global__ void __launch_bounds__(256, 1)
main_kernel(const float* __restrict__ agent, const float* __restrict__ lanes,
            float* __restrict__ out) {
    extern __shared__ float sm[];
    float* s_C = sm + SM_C;
    float* s_S = sm + SM_S;
    float* s_q = sm + SM_Q;
    float* s_r = sm + SM_R;
    float* s_s0 = sm + SM_S0;
    float* s_ax = sm + SM_AX;

    const int tid = threadIdx.x;
    const int bn = blockIdx.x;   // b*64 + n
    const int b = bn >> 6;

    // stage C into smem (17408 floats = 17 float4 per thread, exact)
    {
        const float4* src = (const float4*)g_C;
        float4* dst = (float4*)s_C;
#pragma unroll
        for (int i = 0; i < 17; i++) dst[tid + i * 256] = src[tid + i * 256];
    }
    if (tid < EE) s_q[tid] = g_q[bn * EE + tid];
    if (tid == EE) {
        const float* ag = agent + bn * 16;
        float x = ag[0], y = ag[1], s = ag[3], c = ag[4];
        s_ax[0] = x; s_ax[1] = y; s_ax[2] = s; s_ax[3] = c;
        s_ax[4] = (x == 0.f && y == 0.f && s == 0.f && c == 0.f) ? 0.f : 1.f;
    }
    __syncthreads();

    const float invs = 0.17677669529663687f;  // 1/sqrt(32)
    if (tid < 16) {  // r[h][c] = sum_d WeK[c][h*32+d] q[h*32+d]  (scaled)
        int h = tid >> 2, c = tid & 3;
        float a = 0.f;
        const float* wk = g_WeK + c * EE + h * DHH;
        const float* qp = s_q + h * DHH;
#pragma unroll
        for (int d = 0; d < DHH; d++) a += wk[d] * qp[d];
        s_r[tid] = a * invs;
    } else if (tid < 16 + HH * LL) {  // s0[h*30+l] = q_h . ck[l]_h (scaled)
        int t = tid - 16;
        int h = t / LL, l = t % LL;
        float a = 0.f;
        const float* qp = s_q + h * DHH;
        const float* cp = g_ck + l * EE + h * DHH;
#pragma unroll
        for (int d = 0; d < DHH; d++) a += qp[d] * cp[d];
        s_s0[t] = a * invs;
    }
    __syncthreads();

    // -------- phase B: edge / scores / softmax / ew, write S (k-major) ---
    const int warp = tid >> 5, ln = tid & 31;
    const float ax = s_ax[0], ay = s_ax[1], as1 = s_ax[2], ac1 = s_ax[3], f1 = s_ax[4];
    float rr[16];
#pragma unroll
    for (int i = 0; i < 16; i++) rr[i] = s_r[i];

    const bool act = (ln < LL);

#pragma unroll 1
    for (int mi = 0; mi < 8; mi++) {
        const int m = warp * 8 + mi;
        float ex = 0.f, ey = 0.f, es = 0.f, ec = 0.f;
        float sc[4];
        if (act) {
            const float4 p = *(const float4*)(lanes + ((size_t)(b * MM + m) * LL + ln) * 4);
            float f2 = (p.x == 0.f && p.y == 0.f && p.z == 0.f && p.w == 0.f) ? 0.f : 1.f;
            float f = f1 * f2;
            float dx = p.x - ax, dy = p.y - ay;
            ex = (ac1 * dx + as1 * dy) * 0.1f * f;
            ey = (ac1 * dy - as1 * dx) * 0.1f * f;
            es = (p.z * ac1 - p.w * as1) * f;
            ec = (p.w * ac1 + p.z * as1) * f;
#pragma unroll
            for (int h = 0; h < 4; h++)
                sc[h] = ex * rr[h * 4] + ey * rr[h * 4 + 1] + es * rr[h * 4 + 2] +
                        ec * rr[h * 4 + 3] + s_s0[h * LL + ln];
        } else {
#pragma unroll
            for (int h = 0; h < 4; h++) sc[h] = -1e30f;
        }
        float wgt[4];
#pragma unroll
        for (int h = 0; h < 4; h++) {
            float v = sc[h];
#pragma unroll
            for (int o = 16; o > 0; o >>= 1)
                v = fmaxf(v, __shfl_xor_sync(0xffffffffu, v, o));
            float e = act ? __expf(sc[h] - v) : 0.f;
            float s = e;
#pragma unroll
            for (int o = 16; o > 0; o >>= 1) s += __shfl_xor_sync(0xffffffffu, s, o);
            wgt[h] = e / s;
        }
        if (act) {
#pragma unroll
            for (int h = 0; h < 4; h++) s_S[(h * LL + ln) * SST + m] = wgt[h];
        }
        // ew[h][c] = sum_l wgt[h] * edge[c]
        float p16[16];
#pragma unroll
        for (int h = 0; h < 4; h++) {
            p16[h * 4 + 0] = wgt[h] * ex;
            p16[h * 4 + 1] = wgt[h] * ey;
            p16[h * 4 + 2] = wgt[h] * es;
            p16[h * 4 + 3] = wgt[h] * ec;
        }
#pragma unroll
        for (int i = 0; i < 16; i++) {
            float v = p16[i];
#pragma unroll
            for (int o = 16; o > 0; o >>= 1) v += __shfl_xor_sync(0xffffffffu, v, o);
            p16[i] = v;
        }
        if (ln == 0) {
#pragma unroll
            for (int i = 0; i < 16; i++) s_S[(HH * LL + i) * SST + m] = p16[i];
        }
    }
    __syncthreads();

    // -------- GEMM: OUT[64,128] = S^T[64,136] @ C[136,128] + b2 ----------
    // warp owns m = warp*8..+7 ; lane (te) owns e = te*4..+3
    const int te = ln;
    const int w8 = warp * 8;
    unsigned long long acc[4][4];  // [m-pair][e]
    {
        const float4 bv = *(const float4*)&g_b2[te * 4];
#pragma unroll
        for (int mp = 0; mp < 4; mp++) {
            acc[mp][0] = pk2(bv.x, bv.x);
            acc[mp][1] = pk2(bv.y, bv.y);
            acc[mp][2] = pk2(bv.z, bv.z);
            acc[mp][3] = pk2(bv.w, bv.w);
        }
    }
#pragma unroll 4
    for (int k = 0; k < KD; k++) {
        const float4 c4 = *(const float4*)&s_C[k * EE + te * 4];
        const float4 sA = *(const float4*)&s_S[k * SST + w8];
        const float4 sB = *(const float4*)&s_S[k * SST + w8 + 4];
        unsigned long long cc0 = pk2(c4.x, c4.x), cc1 = pk2(c4.y, c4.y);
        unsigned long long cc2 = pk2(c4.z, c4.z), cc3 = pk2(c4.w, c4.w);
        unsigned long long sp[4] = {pk2(sA.x, sA.y), pk2(sA.z, sA.w),
                                    pk2(sB.x, sB.y), pk2(sB.z, sB.w)};
#pragma unroll
        for (int mp = 0; mp < 4; mp++) {
            fma2(acc[mp][0], sp[mp], cc0);
            fma2(acc[mp][1], sp[mp], cc1);
            fma2(acc[mp][2], sp[mp], cc2);
            fma2(acc[mp][3], sp[mp], cc3);
        }
    }
    // store (coalesced float4 per m row)
    float* outb = out + (size_t)bn * MM * EE;
#pragma unroll
    for (int mp = 0; mp < 4; mp++) {
        float lo0, hi0, lo1, hi1, lo2, hi2, lo3, hi3;
        upk2(acc[mp][0], lo0, hi0);
        upk2(acc[mp][1], lo1, hi1);
        upk2(acc[mp][2], lo2, hi2);
        upk2(acc[mp][3], lo3, hi3);
        int m0 = w8 + mp * 2;
        *(float4*)&outb[(size_t)m0 * EE + te * 4] = make_float4(lo0, lo1, lo2, lo3);
        *(float4*)&outb[(size_t)(m0 + 1) * EE + te * 4] = make_float4(hi0, hi1, hi2, hi3);
    }
}

// =========================== launch ======================================
extern "C" void kernel_launch(void* const* d_in, const int* in_sizes, int n_in,
                              void* d_out, int out_size) {
    const float* agent = (const float*)d_in[0];
    const float* lanes = (const float*)d_in[1];
    const float* We = (const float*)d_in[2];
    const float* be = (const float*)d_in[3];
    const float* Wa = (const float*)d_in[4];
    const float* ba = (const float*)d_in[5];
    const float* pe = (const float*)d_in[6];
    const float* Wq = (const float*)d_in[7];
    const float* bq = (const float*)d_in[8];
    const float* Wk = (const float*)d_in[9];
    const float* bk = (const float*)d_in[10];
    const float* Wv = (const float*)d_in[11];
    const float* bv = (const float*)d_in[12];
    const float* Wo = (const float*)d_in[13];
    const float* bo = (const float*)d_in[14];
    const float* Wp = (const float*)d_in[15];
    const float* bp = (const float*)d_in[16];
    float* outp = (float*)d_out;

    const int smem_bytes = SM_TOTAL_FLOATS * sizeof(float);  // ~107.7 KB
    cudaFuncSetAttribute(main_kernel, cudaFuncAttributeMaxDynamicSharedMemorySize,
                         smem_bytes);

    // P1: 41600 outputs
    p1_kernel<<<163, 256>>>(agent, We, be, Wa, ba, pe, Wk, bk, Wv, bv, Wo, bo, Wp, bp);
    // P2: 33792 outputs
    p2_kernel<<<132, 256>>>(Wq, bq);
    // main: one block per (b,n)
    main_kernel<<<BB * NN, 256, smem_bytes>>>(agent, lanes, outp);
}

// round 4
// speedup vs baseline: 1.0640x; 1.0640x over previous
#include <cuda_runtime.h>
#include <math.h>

// Shapes (fixed per reference)
#define BB 2
#define NN 64
#define MM 64
#define LL 30
#define EE 128
#define HH 4
#define DHH 32
#define KD 136        // 120 softmax-weight rows + 16 ew rows
#define SST 68        // S row stride (64 m, padded)

// ---------------- device scratch (no allocation allowed) ----------------
__device__ __align__(16) float g_W2[EE * EE];     // Wo @ Wp
__device__ __align__(16) float g_WeK[4 * EE];     // We @ Wk
__device__ __align__(16) float g_WeV[4 * EE];     // We @ Wv
__device__ __align__(16) float g_ck[LL * EE];     // (be+pe[l])@Wk + bk
__device__ __align__(16) float g_cv[LL * EE];     // (be+pe[l])@Wv + bv
__device__ __align__(16) float g_b2[EE];          // bo@Wp + bp
__device__ __align__(16) float g_C[KD * EE];      // folded epilogue matrix

// ---------------- f32x2 packed helpers (Blackwell FFMA2) ----------------
__device__ __forceinline__ unsigned long long pk2(float a, float b) {
    unsigned long long r;
    asm("mov.b64 %0, {%1,%2};" : "=l"(r) : "f"(a), "f"(b));
    return r;
}
__device__ __forceinline__ void fma2(unsigned long long& d, unsigned long long a,
                                     unsigned long long b) {
    asm("fma.rn.f32x2 %0, %1, %2, %0;" : "+l"(d) : "l"(a), "l"(b));
}
__device__ __forceinline__ void upk2(unsigned long long v, float& a, float& b) {
    asm("mov.b64 {%0,%1}, %2;" : "=f"(a), "=f"(b) : "l"(v));
}

// ======================= P1: independent precomputes =====================
// outputs: g_W2 (16384), g_WeK (512), g_WeV (512), g_ck (3840), g_cv (3840),
// g_b2 (128). Total 25216 -> 99 blocks x 256.
__global__ void __launch_bounds__(256)
p1_kernel(const float* __restrict__ We, const float* __restrict__ be,
          const float* __restrict__ pe,
          const float* __restrict__ Wk, const float* __restrict__ bk,
          const float* __restrict__ Wv, const float* __restrict__ bv,
          const float* __restrict__ Wo, const float* __restrict__ bo,
          const float* __restrict__ Wp, const float* __restrict__ bp) {
    int id = blockIdx.x * blockDim.x + threadIdx.x;

    if (id < EE * EE) {  // W2[i][j] = sum_t Wo[i][t] Wp[t][j]
        int i = id >> 7, j = id & 127;
        const float* wo = Wo + i * EE;
        const float* wp = Wp + j;
        float a0 = 0.f, a1 = 0.f, a2 = 0.f, a3 = 0.f;
#pragma unroll 8
        for (int t = 0; t < EE; t += 4) {
            a0 = fmaf(wo[t], wp[t * EE], a0);
            a1 = fmaf(wo[t + 1], wp[(t + 1) * EE], a1);
            a2 = fmaf(wo[t + 2], wp[(t + 2) * EE], a2);
            a3 = fmaf(wo[t + 3], wp[(t + 3) * EE], a3);
        }
        g_W2[id] = (a0 + a1) + (a2 + a3);
        return;
    }
    id -= EE * EE;
    if (id < 4 * EE) {  // WeK = We @ Wk
        int c = id >> 7, j = id & 127;
        const float* we = We + c * EE;
        const float* wk = Wk + j;
        float a0 = 0.f, a1 = 0.f, a2 = 0.f, a3 = 0.f;
#pragma unroll 8
        for (int i = 0; i < EE; i += 4) {
            a0 = fmaf(we[i], wk[i * EE], a0);
            a1 = fmaf(we[i + 1], wk[(i + 1) * EE], a1);
            a2 = fmaf(we[i + 2], wk[(i + 2) * EE], a2);
            a3 = fmaf(we[i + 3], wk[(i + 3) * EE], a3);
        }
        g_WeK[id] = (a0 + a1) + (a2 + a3);
        return;
    }
    id -= 4 * EE;
    if (id < 4 * EE) {  // WeV = We @ Wv
        int c = id >> 7, j = id & 127;
        const float* we = We + c * EE;
        const float* wv = Wv + j;
        float a0 = 0.f, a1 = 0.f, a2 = 0.f, a3 = 0.f;
#pragma unroll 8
        for (int i = 0; i < EE; i += 4) {
            a0 = fmaf(we[i], wv[i * EE], a0);
            a1 = fmaf(we[i + 1], wv[(i + 1) * EE], a1);
            a2 = fmaf(we[i + 2], wv[(i + 2) * EE], a2);
            a3 = fmaf(we[i + 3], wv[(i + 3) * EE], a3);
        }
        g_WeV[id] = (a0 + a1) + (a2 + a3);
        return;
    }
    id -= 4 * EE;
    if (id < LL * EE) {  // ck[l][j] = (be+pe[l])@Wk + bk
        int l = id >> 7, j = id & 127;
        const float* pl = pe + l * EE;
        const float* wk = Wk + j;
        float a0 = bk[j], a1 = 0.f, a2 = 0.f, a3 = 0.f;
#pragma unroll 8
        for (int i = 0; i < EE; i += 4) {
            a0 = fmaf(be[i] + pl[i], wk[i * EE], a0);
            a1 = fmaf(be[i + 1] + pl[i + 1], wk[(i + 1) * EE], a1);
            a2 = fmaf(be[i + 2] + pl[i + 2], wk[(i + 2) * EE], a2);
            a3 = fmaf(be[i + 3] + pl[i + 3], wk[(i + 3) * EE], a3);
        }
        g_ck[id] = (a0 + a1) + (a2 + a3);
        return;
    }
    id -= LL * EE;
    if (id < LL * EE) {  // cv[l][j] = (be+pe[l])@Wv + bv
        int l = id >> 7, j = id & 127;
        const float* pl = pe + l * EE;
        const float* wv = Wv + j;
        float a0 = bv[j], a1 = 0.f, a2 = 0.f, a3 = 0.f;
#pragma unroll 8
        for (int i = 0; i < EE; i += 4) {
            a0 = fmaf(be[i] + pl[i], wv[i * EE], a0);
            a1 = fmaf(be[i + 1] + pl[i + 1], wv[(i + 1) * EE], a1);
            a2 = fmaf(be[i + 2] + pl[i + 2], wv[(i + 2) * EE], a2);
            a3 = fmaf(be[i + 3] + pl[i + 3], wv[(i + 3) * EE], a3);
        }
        g_cv[id] = (a0 + a1) + (a2 + a3);
        return;
    }
    id -= LL * EE;
    if (id < EE) {  // b2 = bo@Wp + bp
        const float* wp = Wp + id;
        float a0 = bp[id], a1 = 0.f, a2 = 0.f, a3 = 0.f;
#pragma unroll 8
        for (int t = 0; t < EE; t += 4) {
            a0 = fmaf(bo[t], wp[t * EE], a0);
            a1 = fmaf(bo[t + 1], wp[(t + 1) * EE], a1);
            a2 = fmaf(bo[t + 2], wp[(t + 2) * EE], a2);
            a3 = fmaf(bo[t + 3], wp[(t + 3) * EE], a3);
        }
        g_b2[id] = (a0 + a1) + (a2 + a3);
    }
}

// ======================= P2: C = fold(cv, WeV) with W2 ===================
// 17408 outputs -> 68 blocks x 256
__global__ void __launch_bounds__(256) p2_kernel() {
    int id = blockIdx.x * blockDim.x + threadIdx.x;
    if (id >= KD * EE) return;
    int k = id >> 7, e = id & 127;
    const float* src;
    int h;
    if (k < HH * LL) {
        h = k / LL;
        src = g_cv + (k % LL) * EE + h * DHH;
    } else {
        int kk = k - HH * LL;
        h = kk >> 2;
        src = g_WeV + (kk & 3) * EE + h * DHH;
    }
    const float* w2p = g_W2 + (h * DHH) * EE + e;
    float a0 = 0.f, a1 = 0.f, a2 = 0.f, a3 = 0.f;
#pragma unroll
    for (int d = 0; d < DHH; d += 4) {
        a0 = fmaf(src[d], w2p[d * EE], a0);
        a1 = fmaf(src[d + 1], w2p[(d + 1) * EE], a1);
        a2 = fmaf(src[d + 2], w2p[(d + 2) * EE], a2);
        a3 = fmaf(src[d + 3], w2p[(d + 3) * EE], a3);
    }
    g_C[id] = (a0 + a1) + (a2 + a3);
}

// ======================= main kernel: one block per (b,n) ================
// smem floats: C 17408 | S 136*68=9248 | q 128 | ae 128 | r 16 | s0 120 | ax 8
#define SM_C 0
#define SM_S 17408
#define SM_Q (SM_S + KD * SST)
#define SM_AE (SM_Q + EE)
#define SM_R (SM_AE + EE)
#define SM_S0 (SM_R + 16)
#define SM_AX (SM_S0 + HH * LL)
#define SM_TOTAL_FLOATS (SM_AX + 8)

__global__ void __launch_bounds__(256, 1)
main_kernel(const float* __restrict__ agent, const float* __restrict__ lanes,
            const float* __restrict__ Wa, const float* __restrict__ ba,
            const float* __restrict__ Wq, const float* __restrict__ bq,
            float* __restrict__ out) {
    extern __shared__ float sm[];
    float* s_C = sm + SM_C;
    float* s_S = sm + SM_S;
    float* s_q = sm + SM_Q;
    float* s_ae = sm + SM_AE;
    float* s_r = sm + SM_R;
    float* s_s0 = sm + SM_S0;
    float* s_ax = sm + SM_AX;

    const int tid = threadIdx.x;
    const int bn = blockIdx.x;   // b*64 + n
    const int b = bn >> 6;

    // stage C into smem (17408 floats = 17 float4 per thread, exact)
    {
        const float4* src = (const float4*)g_C;
        float4* dst = (float4*)s_C;
#pragma unroll
        for (int i = 0; i < 17; i++) dst[tid + i * 256] = src[tid + i * 256];
    }
    // ae = afeat@Wa + ba  (128 outputs)
    if (tid < EE) {
        const float* ag = agent + bn * 16;
        float a = fmaf(ag[2], Wa[tid], ba[tid]);
#pragma unroll
        for (int i = 1; i < 12; i++) a = fmaf(ag[4 + i], Wa[i * EE + tid], a);
        s_ae[tid] = a;
    }
    if (tid == EE) {
        const float* ag = agent + bn * 16;
        float x = ag[0], y = ag[1], s = ag[3], c = ag[4];
        s_ax[0] = x; s_ax[1] = y; s_ax[2] = s; s_ax[3] = c;
        s_ax[4] = (x == 0.f && y == 0.f && s == 0.f && c == 0.f) ? 0.f : 1.f;
    }
    __syncthreads();

    // q = ae@Wq + bq  (128 outputs)
    if (tid < EE) {
        const float* wq = Wq + tid;
        float a0 = bq[tid], a1 = 0.f, a2 = 0.f, a3 = 0.f;
#pragma unroll 8
        for (int i = 0; i < EE; i += 4) {
            a0 = fmaf(s_ae[i], wq[i * EE], a0);
            a1 = fmaf(s_ae[i + 1], wq[(i + 1) * EE], a1);
            a2 = fmaf(s_ae[i + 2], wq[(i + 2) * EE], a2);
            a3 = fmaf(s_ae[i + 3], wq[(i + 3) * EE], a3);
        }
        s_q[tid] = (a0 + a1) + (a2 + a3);
    }
    __syncthreads();

    const float invs = 0.17677669529663687f;  // 1/sqrt(32)
    if (tid < 16) {  // r[h][c] = sum_d WeK[c][h*32+d] q[h*32+d]  (scaled)
        int h = tid >> 2, c = tid & 3;
        const float* wk = g_WeK + c * EE + h * DHH;
        const float* qp = s_q + h * DHH;
        float a0 = 0.f, a1 = 0.f, a2 = 0.f, a3 = 0.f;
#pragma unroll
        for (int d = 0; d < DHH; d += 4) {
            a0 = fmaf(wk[d], qp[d], a0);
            a1 = fmaf(wk[d + 1], qp[d + 1], a1);
            a2 = fmaf(wk[d + 2], qp[d + 2], a2);
            a3 = fmaf(wk[d + 3], qp[d + 3], a3);
        }
        s_r[tid] = ((a0 + a1) + (a2 + a3)) * invs;
    } else if (tid < 16 + HH * LL) {  // s0[h*30+l] = q_h . ck[l]_h (scaled)
        int t = tid - 16;
        int h = t / LL, l = t % LL;
        const float* qp = s_q + h * DHH;
        const float* cp = g_ck + l * EE + h * DHH;
        float a0 = 0.f, a1 = 0.f, a2 = 0.f, a3 = 0.f;
#pragma unroll
        for (int d = 0; d < DHH; d += 4) {
            a0 = fmaf(qp[d], cp[d], a0);
            a1 = fmaf(qp[d + 1], cp[d + 1], a1);
            a2 = fmaf(qp[d + 2], cp[d + 2], a2);
            a3 = fmaf(qp[d + 3], cp[d + 3], a3);
        }
        s_s0[t] = ((a0 + a1) + (a2 + a3)) * invs;
    }
    __syncthreads();

    // -------- phase B: edge / scores / softmax / ew, write S (k-major) ---
    const int warp = tid >> 5, ln = tid & 31;
    const float ax = s_ax[0], ay = s_ax[1], as1 = s_ax[2], ac1 = s_ax[3], f1 = s_ax[4];
    float rr[16];
#pragma unroll
    for (int i = 0; i < 16; i++) rr[i] = s_r[i];

    const bool act = (ln < LL);

#pragma unroll 1
    for (int mi = 0; mi < 8; mi++) {
        const int m = warp * 8 + mi;
        float ex = 0.f, ey = 0.f, es = 0.f, ec = 0.f;
        float sc[4];
        if (act) {
            const float4 p = *(const float4*)(lanes + ((size_t)(b * MM + m) * LL + ln) * 4);
            float f2 = (p.x == 0.f && p.y == 0.f && p.z == 0.f && p.w == 0.f) ? 0.f : 1.f;
            float f = f1 * f2;
            float dx = p.x - ax, dy = p.y - ay;
            ex = (ac1 * dx + as1 * dy) * 0.1f * f;
            ey = (ac1 * dy - as1 * dx) * 0.1f * f;
            es = (p.z * ac1 - p.w * as1) * f;
            ec = (p.w * ac1 + p.z * as1) * f;
#pragma unroll
            for (int h = 0; h < 4; h++)
                sc[h] = ex * rr[h * 4] + ey * rr[h * 4 + 1] + es * rr[h * 4 + 2] +
                        ec * rr[h * 4 + 3] + s_s0[h * LL + ln];
        } else {
#pragma unroll
            for (int h = 0; h < 4; h++) sc[h] = -1e30f;
        }
        float wgt[4];
#pragma unroll
        for (int h = 0; h < 4; h++) {
            float v = sc[h];
#pragma unroll
            for (int o = 16; o > 0; o >>= 1)
                v = fmaxf(v, __shfl_xor_sync(0xffffffffu, v, o));
            float e = act ? __expf(sc[h] - v) : 0.f;
            float s = e;
#pragma unroll
            for (int o = 16; o > 0; o >>= 1) s += __shfl_xor_sync(0xffffffffu, s, o);
            wgt[h] = e / s;
        }
        if (act) {
#pragma unroll
            for (int h = 0; h < 4; h++) s_S[(h * LL + ln) * SST + m] = wgt[h];
        }
        // ew[h][c] = sum_l wgt[h] * edge[c]
        float p16[16];
#pragma unroll
        for (int h = 0; h < 4; h++) {
            p16[h * 4 + 0] = wgt[h] * ex;
            p16[h * 4 + 1] = wgt[h] * ey;
            p16[h * 4 + 2] = wgt[h] * es;
            p16[h * 4 + 3] = wgt[h] * ec;
        }
#pragma unroll
        for (int i = 0; i < 16; i++) {
            float v = p16[i];
#pragma unroll
            for (int o = 16; o > 0; o >>= 1) v += __shfl_xor_sync(0xffffffffu, v, o);
            p16[i] = v;
        }
        if (ln == 0) {
#pragma unroll
            for (int i = 0; i < 16; i++) s_S[(HH * LL + i) * SST + m] = p16[i];
        }
    }
    __syncthreads();

    // -------- GEMM: OUT[64,128] = S^T[64,136] @ C[136,128] + b2 ----------
    // warp owns m = warp*8..+7 ; lane (te) owns e = te*4..+3
    const int te = ln;
    const int w8 = warp * 8;
    unsigned long long acc[4][4];  // [m-pair][e]
    {
        const float4 bvv = *(const float4*)&g_b2[te * 4];
#pragma unroll
        for (int mp = 0; mp < 4; mp++) {
            acc[mp][0] = pk2(bvv.x, bvv.x);
            acc[mp][1] = pk2(bvv.y, bvv.y);
            acc[mp][2] = pk2(bvv.z, bvv.z);
            acc[mp][3] = pk2(bvv.w, bvv.w);
        }
    }
#pragma unroll 4
    for (int k = 0; k < KD; k++) {
        const float4 c4 = *(const float4*)&s_C[k * EE + te * 4];
        const float4 sA = *(const float4*)&s_S[k * SST + w8];
        const float4 sB = *(const float4*)&s_S[k * SST + w8 + 4];
        unsigned long long cc0 = pk2(c4.x, c4.x), cc1 = pk2(c4.y, c4.y);
        unsigned long long cc2 = pk2(c4.z, c4.z), cc3 = pk2(c4.w, c4.w);
        unsigned long long sp[4] = {pk2(sA.x, sA.y), pk2(sA.z, sA.w),
                                    pk2(sB.x, sB.y), pk2(sB.z, sB.w)};
#pragma unroll
        for (int mp = 0; mp < 4; mp++) {
            fma2(acc[mp][0], sp[mp], cc0);
            fma2(acc[mp][1], sp[mp], cc1);
            fma2(acc[mp][2], sp[mp], cc2);
            fma2(acc[mp][3], sp[mp], cc3);
        }
    }
    // store (coalesced float4 per m row)
    float* outb = out + (size_t)bn * MM * EE;
#pragma unroll
    for (int mp = 0; mp < 4; mp++) {
        float lo0, hi0, lo1, hi1, lo2, hi2, lo3, hi3;
        upk2(acc[mp][0], lo0, hi0);
        upk2(acc[mp][1], lo1, hi1);
        upk2(acc[mp][2], lo2, hi2);
        upk2(acc[mp][3], lo3, hi3);
        int m0 = w8 + mp * 2;
        *(float4*)&outb[(size_t)m0 * EE + te * 4] = make_float4(lo0, lo1, lo2, lo3);
        *(float4*)&outb[(size_t)(m0 + 1) * EE + te * 4] = make_float4(hi0, hi1, hi2, hi3);
    }
}

// =========================== launch ======================================
extern "C" void kernel_launch(void* const* d_in, const int* in_sizes, int n_in,
                              void* d_out, int out_size) {
    const float* agent = (const float*)d_in[0];
    const float* lanes = (const float*)d_in[1];
    const float* We = (const float*)d_in[2];
    const float* be = (const float*)d_in[3];
    const float* Wa = (const float*)d_in[4];
    const float* ba = (const float*)d_in[5];
    const float* pe = (const float*)d_in[6];
    const float* Wq = (const float*)d_in[7];
    const float* bq = (const float*)d_in[8];
    const float* Wk = (const float*)d_in[9];
    const float* bk = (const float*)d_in[10];
    const float* Wv = (const float*)d_in[11];
    const float* bv = (const float*)d_in[12];
    const float* Wo = (const float*)d_in[13];
    const float* bo = (const float*)d_in[14];
    const float* Wp = (const float*)d_in[15];
    const float* bp = (const float*)d_in[16];
    float* outp = (float*)d_out;

    const int smem_bytes = SM_TOTAL_FLOATS * sizeof(float);  // ~108.3 KB
    cudaFuncSetAttribute(main_kernel, cudaFuncAttributeMaxDynamicSharedMemorySize,
                         smem_bytes);

    // P1: 25216 outputs
    p1_kernel<<<99, 256>>>(We, be, pe, Wk, bk, Wv, bv, Wo, bo, Wp, bp);
    // P2: 17408 outputs
    p2_kernel<<<68, 256>>>();
    // main: one block per (b,n)
    main_kernel<<<BB * NN, 256, smem_bytes>>>(agent, lanes, Wa, ba, Wq, bq, outp);
}